// round 15
// baseline (speedup 1.0000x reference)
#include <cuda_runtime.h>
#include <math.h>

// B=4096, N=16384, fp32. HBM-bound stencil:
//   x = nan_checker(output); g[i] = x[i]-x[(i-1)%N];
//   out = (|g - mean| > 4*sqrt(var)) ? 0 : x    [via (g-m)^2 > 16*var]
//
// FINAL (champion config, best measured bench 80.96us / kernel 74.7us /
// DRAM 81.4% = the measured mixed R+W HBM ceiling on sm_103a):
//   - one v8 (256-bit) load/store per thread; 4 memory instrs/thread total
//   - squared compare eliminates per-element MUFU sqrt
//   - left neighbor via warp shuffle; lane0 does one L2-hit scalar load
//   - TPB=512 (128KB contiguous slab/CTA), grid (4, 4096) = 16384 CTAs
//   - x/stats: ld.global.nc; out: st.global.cs

#define K_SIGMA 4.0f
#define K2 (K_SIGMA * K_SIGMA)   // 16
#define TPB 512

__device__ __forceinline__ float sanitize(float v) {
    return isfinite(v) ? v : 0.0f;
}

__device__ __forceinline__ void ldg_nc_v8(const float* p, float* r) {
    asm volatile(
        "ld.global.nc.v8.f32 {%0,%1,%2,%3,%4,%5,%6,%7}, [%8];"
        : "=f"(r[0]), "=f"(r[1]), "=f"(r[2]), "=f"(r[3]),
          "=f"(r[4]), "=f"(r[5]), "=f"(r[6]), "=f"(r[7])
        : "l"(p));
}

__device__ __forceinline__ void stg_cs_v8(float* p, const float* r) {
    asm volatile(
        "st.global.cs.v8.f32 [%0], {%1,%2,%3,%4,%5,%6,%7,%8};"
        :: "l"(p),
           "f"(r[0]), "f"(r[1]), "f"(r[2]), "f"(r[3]),
           "f"(r[4]), "f"(r[5]), "f"(r[6]), "f"(r[7])
        : "memory");
}

__global__ __launch_bounds__(TPB)
void correction_kernel(const float* __restrict__ x,
                       const float* __restrict__ mean_grad,
                       const float* __restrict__ var_grad,
                       float* __restrict__ out,
                       int N)
{
    const int row = blockIdx.y;
    const long long rowOff = (long long)row * N;
    const int cv = blockIdx.x * TPB + threadIdx.x;   // v8 index in row
    const long long col0 = (long long)cv * 8;
    const unsigned lane = threadIdx.x & 31u;

    float r[8], m[8], vv[8];
    ldg_nc_v8(x + rowOff + col0, r);
    ldg_nc_v8(mean_grad + col0, m);
    ldg_nc_v8(var_grad + col0, vv);

    #pragma unroll
    for (int j = 0; j < 8; j++) r[j] = sanitize(r[j]);

    // Left neighbor of element 0: previous lane's element 7 (lane 0 does
    // one L2-hit scalar load of the adjacent sector; circular at col 0).
    float prev = __shfl_up_sync(0xFFFFFFFFu, r[7], 1);
    if (lane == 0) {
        long long pc = (cv == 0) ? (N - 1) : (col0 - 1);
        prev = sanitize(__ldg(&x[rowOff + pc]));
    }

    float o[8];
    #pragma unroll
    for (int j = 0; j < 8; j++) {
        float p = (j == 0) ? prev : r[j - 1];
        float d = (r[j] - p) - m[j];
        // mask iff (g-m)^2 > 16*var  <=>  |g-m| > 4*sqrt(var)
        o[j] = (d * d > K2 * vv[j]) ? 0.0f : r[j];
    }

    stg_cs_v8(out + rowOff + col0, o);
}

extern "C" void kernel_launch(void* const* d_in, const int* in_sizes, int n_in,
                              void* d_out, int out_size) {
    const float* x         = (const float*)d_in[0];
    const float* mean_grad = (const float*)d_in[1];
    const float* var_grad  = (const float*)d_in[2];
    float* out             = (float*)d_out;

    int N = in_sizes[1];                       // 16384
    long long total = (long long)in_sizes[0];  // B*N
    int B = (int)(total / N);

    int vecsPerRow = N / 8;                    // 2048
    dim3 grid(vecsPerRow / TPB, B);            // (4, 4096) = 16384 blocks
    correction_kernel<<<grid, TPB>>>(x, mean_grad, var_grad, out, N);
}

// round 16
// speedup vs baseline: 1.0159x; 1.0159x over previous
#include <cuda_runtime.h>
#include <math.h>

// B=4096, N=16384, fp32. HBM-bound stencil:
//   x = nan_checker(output); g[i] = x[i]-x[(i-1)%N];
//   out = (|g - mean| > 4*sqrt(var)) ? 0 : x    [via (g-m)^2 > 16*var]
//
// FINAL champion (best measured bench 80.96us / kernel 74.7us / DRAM 81.4%
// = the measured mixed R+W HBM ceiling on sm_103a; R13..R16 byte-identical
// resubmissions bracket run noise at ~±1us):
//   - one v8 (256-bit) load/store per thread; 4 memory instrs/thread total
//   - squared compare eliminates per-element MUFU sqrt
//   - left neighbor via warp shuffle; lane0 does one L2-hit scalar load
//   - TPB=512 (128KB contiguous slab/CTA), grid (4, 4096) = 16384 CTAs
//   - x/stats: ld.global.nc; out: st.global.cs

#define K_SIGMA 4.0f
#define K2 (K_SIGMA * K_SIGMA)   // 16
#define TPB 512

__device__ __forceinline__ float sanitize(float v) {
    return isfinite(v) ? v : 0.0f;
}

__device__ __forceinline__ void ldg_nc_v8(const float* p, float* r) {
    asm volatile(
        "ld.global.nc.v8.f32 {%0,%1,%2,%3,%4,%5,%6,%7}, [%8];"
        : "=f"(r[0]), "=f"(r[1]), "=f"(r[2]), "=f"(r[3]),
          "=f"(r[4]), "=f"(r[5]), "=f"(r[6]), "=f"(r[7])
        : "l"(p));
}

__device__ __forceinline__ void stg_cs_v8(float* p, const float* r) {
    asm volatile(
        "st.global.cs.v8.f32 [%0], {%1,%2,%3,%4,%5,%6,%7,%8};"
        :: "l"(p),
           "f"(r[0]), "f"(r[1]), "f"(r[2]), "f"(r[3]),
           "f"(r[4]), "f"(r[5]), "f"(r[6]), "f"(r[7])
        : "memory");
}

__global__ __launch_bounds__(TPB)
void correction_kernel(const float* __restrict__ x,
                       const float* __restrict__ mean_grad,
                       const float* __restrict__ var_grad,
                       float* __restrict__ out,
                       int N)
{
    const int row = blockIdx.y;
    const long long rowOff = (long long)row * N;
    const int cv = blockIdx.x * TPB + threadIdx.x;   // v8 index in row
    const long long col0 = (long long)cv * 8;
    const unsigned lane = threadIdx.x & 31u;

    float r[8], m[8], vv[8];
    ldg_nc_v8(x + rowOff + col0, r);
    ldg_nc_v8(mean_grad + col0, m);
    ldg_nc_v8(var_grad + col0, vv);

    #pragma unroll
    for (int j = 0; j < 8; j++) r[j] = sanitize(r[j]);

    // Left neighbor of element 0: previous lane's element 7 (lane 0 does
    // one L2-hit scalar load of the adjacent sector; circular at col 0).
    float prev = __shfl_up_sync(0xFFFFFFFFu, r[7], 1);
    if (lane == 0) {
        long long pc = (cv == 0) ? (N - 1) : (col0 - 1);
        prev = sanitize(__ldg(&x[rowOff + pc]));
    }

    float o[8];
    #pragma unroll
    for (int j = 0; j < 8; j++) {
        float p = (j == 0) ? prev : r[j - 1];
        float d = (r[j] - p) - m[j];
        // mask iff (g-m)^2 > 16*var  <=>  |g-m| > 4*sqrt(var)
        o[j] = (d * d > K2 * vv[j]) ? 0.0f : r[j];
    }

    stg_cs_v8(out + rowOff + col0, o);
}

extern "C" void kernel_launch(void* const* d_in, const int* in_sizes, int n_in,
                              void* d_out, int out_size) {
    const float* x         = (const float*)d_in[0];
    const float* mean_grad = (const float*)d_in[1];
    const float* var_grad  = (const float*)d_in[2];
    float* out             = (float*)d_out;

    int N = in_sizes[1];                       // 16384
    long long total = (long long)in_sizes[0];  // B*N
    int B = (int)(total / N);

    int vecsPerRow = N / 8;                    // 2048
    dim3 grid(vecsPerRow / TPB, B);            // (4, 4096) = 16384 blocks
    correction_kernel<<<grid, TPB>>>(x, mean_grad, var_grad, out, N);
}